// round 15
// baseline (speedup 1.0000x reference)
#include <cuda_runtime.h>
#include <cuda_bf16.h>
#include <cuda_fp16.h>
#include <cstdint>

#define BH    32
#define NSEQ  4096
#define DDIM  64
#define MFEAT 266
#define MP    320
#define NT    32
#define KSPL  16
#define KSEG  (NSEQ / KSPL)

#define DNORM   0.35355339059327373f
#define RATIO_C 0.061313933948496576f
#define REPS_C  6.1313933948496576e-06f   // ratio * 1e-4
#define NEGINF  -1.0e30f

// ---------------- global scratch (static; no cudaMalloc) --------------------
__device__ float        g_ctxS[(size_t)KSPL * BH * 72 * MP];   // K-split ctx^T partials
__device__ float        g_ctxM[KSPL * BH * 3];                 // per (slab, mtile) stabilizer
__device__ float        g_ctxsum[BH * 72];                     // sum_m ctx[m,e]
__device__ uint32_t     g_ctf[(size_t)BH * 72 * 160];          // ctx^T fp16 pairs
__device__ uint32_t     g_pjf[384 * 32];                       // proj fp16 pairs (padded rows)
__device__ unsigned int g_kmax_enc;

__device__ __forceinline__ unsigned int enc_f(float f) {
    unsigned int u = __float_as_uint(f);
    return (u & 0x80000000u) ? ~u : (u | 0x80000000u);
}
__device__ __forceinline__ float dec_f(unsigned int k) {
    return (k & 0x80000000u) ? __uint_as_float(k & 0x7fffffffu) : __uint_as_float(~k);
}
__device__ __forceinline__ uint32_t smem_u32(const void* p) {
    uint32_t a;
    asm("{ .reg .u64 t; cvta.to.shared.u64 t, %1; cvt.u32.u64 %0, t; }" : "=r"(a) : "l"(p));
    return a;
}
__device__ __forceinline__ uint32_t packh2(float a, float b) {
    __half2 t = __floats2half2_rn(a, b);
    return reinterpret_cast<uint32_t&>(t);
}
// fp16 hi/lo split: hi = rn(x), lo = rn(x - hi). Reconstruction exact to ~2^-23.
__device__ __forceinline__ void split2h(float a, float b, uint32_t& hi, uint32_t& lo) {
    __half ha = __float2half_rn(a), hb = __float2half_rn(b);
    float ra = a - __half2float(ha), rb = b - __half2float(hb);
    __half2 H; H.x = ha; H.y = hb;
    hi = reinterpret_cast<uint32_t&>(H);
    lo = packh2(ra, rb);
}

// ---------------- cp.async helpers ------------------------------------------
__device__ __forceinline__ void cp16(uint32_t saddr, const void* gptr) {
    asm volatile("cp.async.cg.shared.global [%0], [%1], 16;" :: "r"(saddr), "l"(gptr));
}
#define CP_COMMIT() asm volatile("cp.async.commit_group;" ::: "memory")
#define CP_WAIT0()  asm volatile("cp.async.wait_group 0;" ::: "memory")

// ---------------- mma.sync + ldmatrix helpers -------------------------------
__device__ __forceinline__ void ldsm_x4(uint32_t* r, uint32_t addr) {
    asm volatile("ldmatrix.sync.aligned.m8n8.x4.shared.b16 {%0,%1,%2,%3}, [%4];"
        : "=r"(r[0]), "=r"(r[1]), "=r"(r[2]), "=r"(r[3]) : "r"(addr));
}
__device__ __forceinline__ void ldsm_x2(uint32_t* r, uint32_t addr) {
    asm volatile("ldmatrix.sync.aligned.m8n8.x2.shared.b16 {%0,%1}, [%2];"
        : "=r"(r[0]), "=r"(r[1]) : "r"(addr));
}
__device__ __forceinline__ void ldsm_x4t(uint32_t* r, uint32_t addr) {
    asm volatile("ldmatrix.sync.aligned.m8n8.x4.trans.shared.b16 {%0,%1,%2,%3}, [%4];"
        : "=r"(r[0]), "=r"(r[1]), "=r"(r[2]), "=r"(r[3]) : "r"(addr));
}
__device__ __forceinline__ void ldsm_x2t(uint32_t* r, uint32_t addr) {
    asm volatile("ldmatrix.sync.aligned.m8n8.x2.trans.shared.b16 {%0,%1}, [%2];"
        : "=r"(r[0]), "=r"(r[1]) : "r"(addr));
}
__device__ __forceinline__ void mma_f16(float* c, const uint32_t* a, const uint32_t* b) {
    asm volatile("mma.sync.aligned.m16n8k16.row.col.f32.f16.f16.f32 "
        "{%0,%1,%2,%3}, {%4,%5,%6,%7}, {%8,%9}, {%0,%1,%2,%3};"
        : "+f"(c[0]), "+f"(c[1]), "+f"(c[2]), "+f"(c[3])
        : "r"(a[0]), "r"(a[1]), "r"(a[2]), "r"(a[3]), "r"(b[0]), "r"(b[1]));
}

// ---------------------------------------------------------------------------
__global__ void init_kernel() {
    if (threadIdx.x == 0 && blockIdx.x == 0) g_kmax_enc = 0u;
}

// prep_proj: proj -> single fp16 pairs, rows padded to 384 with zeros.
__global__ void prep_proj(const float* __restrict__ proj) {
    int i = blockIdx.x * blockDim.x + threadIdx.x;
    if (i >= 384 * 32) return;
    int r = i >> 5, p = i & 31;
    float2 v = (r < MFEAT) ? *(const float2*)(proj + r * 64 + 2 * p) : make_float2(0.f, 0.f);
    g_pjf[i] = packh2(v.x, v.y);
}

// ---------------------------------------------------------------------------
// ctx_fused: ddT = proj(fp16 hi/lo split) @ k(single fp16)^T, 2-term fp16.
// Then block max -> rescale -> kp fp16 in regs -> GEMM2 kpT @ [v|1] fp16.
// grid (3*KSPL, BH), block 256, 2 CTAs/SM.
// ---------------------------------------------------------------------------
#define CP_H 0
#define CP_L 18432
#define CK_  36864
#define CW_  46080
#define CD_  57344
#define C_MX 57600
#define CX_SZ 57664

__global__ void __launch_bounds__(256, 2) ctx_fused(const float* __restrict__ k_in,
                                                    const float* __restrict__ v_in,
                                                    const float* __restrict__ proj) {
    extern __shared__ char smem[];
    uint32_t sb = smem_u32(smem);
    int tid = threadIdx.x, w = tid >> 5, lane = tid & 31;
    int bh = blockIdx.y, mtile = blockIdx.x % 3, ks = blockIdx.x / 3;

    int arow = lane & 15, koff = (lane >> 4) * 16;
    int br7 = lane & 7, bk8 = ((lane >> 3) & 1) * 16;
    int mh16 = (lane >> 4) & 1;
    int krb  = (lane & 7) + 8 * ((lane >> 3) & 1);
    int qrow = lane >> 2, qcol2 = 2 * (lane & 3);
    int tileid = 8 * mtile + w;
    bool wvalid = tileid <= 16;
    int mr0 = mtile * 128 + 16 * w + qrow;

    // stage proj tile [128 m rows x 64 d] fp16 hi/lo (persistent)
    for (int i = tid; i < 128 * 32; i += 256) {
        int r = i >> 5, p = i & 31;
        int m = mtile * 128 + r;
        float2 v = (m < MFEAT) ? *(const float2*)(proj + m * 64 + 2 * p) : make_float2(0.f, 0.f);
        uint32_t hi, lo; split2h(v.x, v.y, hi, lo);
        *(uint32_t*)(smem + CP_H + r * 144 + 4 * p) = hi;
        *(uint32_t*)(smem + CP_L + r * 144 + 4 * p) = lo;
    }

    float accC[9][4];
    #pragma unroll
    for (int n = 0; n < 9; n++)
        #pragma unroll
        for (int x = 0; x < 4; x++) accC[n][x] = 0.f;
    float Mold = NEGINF;

    #pragma unroll 1
    for (int c = 0; c < KSEG / 64; c++) {
        int n0 = ks * KSEG + c * 64;
        __syncthreads();
        const float* kb = k_in + ((size_t)bh * NSEQ + n0) * DDIM;
        for (int i = tid; i < 64 * 32; i += 256) {
            int r = i >> 5, p = i & 31;
            float2 v = *(const float2*)(kb + r * 64 + 2 * p);
            *(uint32_t*)(smem + CK_ + r * 144 + 4 * p) = packh2(DNORM * v.x, DNORM * v.y);
        }
        const float* vb = v_in + ((size_t)bh * NSEQ + n0) * DDIM;
        for (int i = tid; i < 64 * 36; i += 256) {
            int r = i / 36, p = i % 36;
            int e = 2 * p;
            float2 wv;
            if (e < 64)       wv = *(const float2*)(vb + r * 64 + e);
            else if (e == 64) wv = make_float2(1.f, 0.f);
            else              wv = make_float2(0.f, 0.f);
            *(uint32_t*)(smem + CW_ + r * 176 + 4 * p) = packh2(wv.x, wv.y);
        }
        // diag from fp32 global k (exact; rows L1-hot from staging reads)
        if (tid < 64) {
            float s = 0.f;
            #pragma unroll
            for (int d = 0; d < DDIM; d++) { float x = kb[tid * 64 + d]; s += x * x; }
            ((float*)(smem + CD_))[tid] = 0.0625f * s;
        }
        __syncthreads();

        // GEMM1': ddT[16 rows x 64 n], 2-term fp16 (A split, B single)
        float c1[8][4];
        #pragma unroll
        for (int n = 0; n < 8; n++)
            #pragma unroll
            for (int x = 0; x < 4; x++) c1[n][x] = 0.f;
        if (wvalid) {
            #pragma unroll
            for (int kt = 0; kt < 4; kt++) {
                uint32_t aph[4], apl[4];
                uint32_t a = sb + CP_H + (uint32_t)(16 * w + arow) * 144 + kt * 32 + koff;
                ldsm_x4(aph, a);
                ldsm_x4(apl, a + (CP_L - CP_H));
                uint32_t bk[8][2];
                #pragma unroll
                for (int np = 0; np < 4; np++) {
                    uint32_t nrow = (uint32_t)(8 * (2 * np + mh16) + br7);
                    ldsm_x4(&bk[2 * np][0], sb + CK_ + nrow * 144 + kt * 32 + bk8);
                }
                #pragma unroll
                for (int n = 0; n < 8; n++) {
                    mma_f16(c1[n], aph, bk[n]);
                    mma_f16(c1[n], apl, bk[n]);
                }
            }
        }

        bool v0 = wvalid && (mr0 < MFEAT), v1 = wvalid && (mr0 + 8 < MFEAT);
        float lm = NEGINF;
        #pragma unroll
        for (int n = 0; n < 8; n++) {
            if (v0) lm = fmaxf(lm, fmaxf(c1[n][0], c1[n][1]));
            if (v1) lm = fmaxf(lm, fmaxf(c1[n][2], c1[n][3]));
        }
        #pragma unroll
        for (int off = 16; off; off >>= 1) lm = fmaxf(lm, __shfl_xor_sync(0xffffffffu, lm, off));
        if (lane == 0) ((float*)(smem + C_MX))[w] = lm;
        __syncthreads();
        float bmax = NEGINF;
        #pragma unroll
        for (int i = 0; i < 8; i++) bmax = fmaxf(bmax, ((float*)(smem + C_MX))[i]);
        float Mnew = fmaxf(Mold, bmax);

        if (wvalid) {
            float factor = __expf(Mold - Mnew);
            float f0 = (mr0 == MFEAT) ? 1.f : factor;
            float f1 = (mr0 + 8 == MFEAT) ? 1.f : factor;
            #pragma unroll
            for (int n = 0; n < 9; n++) {
                accC[n][0] *= f0; accC[n][1] *= f0;
                accC[n][2] *= f1; accC[n][3] *= f1;
            }

            float* dg = (float*)(smem + CD_);
            #pragma unroll
            for (int kt2 = 0; kt2 < 4; kt2++) {
                int u = 2 * kt2, vt = u + 1;
                int ncol = 16 * kt2 + qcol2;
                float dgu0 = dg[ncol],     dgu1 = dg[ncol + 1];
                float dgv0 = dg[ncol + 8], dgv1 = dg[ncol + 9];
                uint32_t qa[4];
                {
                    float a0, a1, a2, a3;
                    if (mr0 < MFEAT) {
                        a0 = RATIO_C * __expf(c1[u][0] - dgu0 - Mnew);
                        a1 = RATIO_C * __expf(c1[u][1] - dgu1 - Mnew);
                        a2 = RATIO_C * __expf(c1[vt][0] - dgv0 - Mnew);
                        a3 = RATIO_C * __expf(c1[vt][1] - dgv1 - Mnew);
                    } else if (mr0 == MFEAT) { a0 = a1 = a2 = a3 = 1.f; }
                    else { a0 = a1 = a2 = a3 = 0.f; }
                    qa[0] = packh2(a0, a1); qa[2] = packh2(a2, a3);
                }
                {
                    int m1 = mr0 + 8;
                    float a0, a1, a2, a3;
                    if (m1 < MFEAT) {
                        a0 = RATIO_C * __expf(c1[u][2] - dgu0 - Mnew);
                        a1 = RATIO_C * __expf(c1[u][3] - dgu1 - Mnew);
                        a2 = RATIO_C * __expf(c1[vt][2] - dgv0 - Mnew);
                        a3 = RATIO_C * __expf(c1[vt][3] - dgv1 - Mnew);
                    } else if (m1 == MFEAT) { a0 = a1 = a2 = a3 = 1.f; }
                    else { a0 = a1 = a2 = a3 = 0.f; }
                    qa[1] = packh2(a0, a1); qa[3] = packh2(a2, a3);
                }
                uint32_t bwh[9][2];
                uint32_t wrow = sb + CW_ + (uint32_t)(kt2 * 16 + krb) * 176;
                #pragma unroll
                for (int np = 0; np < 4; np++)
                    ldsm_x4t(&bwh[2 * np][0], wrow + 16 * (uint32_t)(2 * np + mh16));
                ldsm_x2t(bwh[8], wrow + 128);
                #pragma unroll
                for (int nE = 0; nE < 9; nE++)
                    mma_f16(accC[nE], qa, bwh[nE]);
            }
        }
        Mold = Mnew;
    }

    if (wvalid) {
        float* slab = g_ctxS + ((size_t)(ks * BH + bh)) * 72 * MP;
        #pragma unroll
        for (int nE = 0; nE < 9; nE++) {
            int e = 8 * nE + qcol2;
            slab[(size_t)e * MP + mr0]           = accC[nE][0];
            slab[(size_t)(e + 1) * MP + mr0]     = accC[nE][1];
            slab[(size_t)e * MP + mr0 + 8]       = accC[nE][2];
            slab[(size_t)(e + 1) * MP + mr0 + 8] = accC[nE][3];
        }
    }
    if (tid == 0) {
        g_ctxM[(ks * BH + bh) * 3 + mtile] = Mold;
        atomicMax(&g_kmax_enc, enc_f(Mold));
    }
}

// ---------------------------------------------------------------------------
// convert: merge slabs with e^{M_s,mt - G}; analytic EPS; fp16 pack; ctxsum.
// ---------------------------------------------------------------------------
__global__ void __launch_bounds__(160) convert_kernel() {
    __shared__ float sc[KSPL * 3];
    __shared__ float vs_sh;
    __shared__ float red[5];
    int e = blockIdx.x, bh = blockIdx.y, t = threadIdx.x;
    float G = dec_f(g_kmax_enc);
    if (t < KSPL * 3) sc[t] = __expf(g_ctxM[(t / 3 * BH + bh) * 3 + (t % 3)] - G);
    if (t == 0) {
        float v = 0.f;
        #pragma unroll
        for (int ks = 0; ks < KSPL; ks++)
            v += g_ctxS[(((size_t)(ks * BH + bh)) * 72 + e) * MP + MFEAT];
        vs_sh = v;
    }
    __syncthreads();

    int mt = t >> 6;
    int m0 = 2 * t;
    float sx = 0.f, sy = 0.f;
    if (m0 < 272) {
        #pragma unroll
        for (int ks = 0; ks < KSPL; ks++) {
            float2 vv = *(const float2*)(g_ctxS + (((size_t)(ks * BH + bh)) * 72 + e) * MP + m0);
            float s = sc[ks * 3 + mt];
            sx += s * vv.x; sy += s * vv.y;
        }
    }
    float eps_add = REPS_C * vs_sh;
    float fx = (m0     < MFEAT) ? sx + eps_add : 0.f;
    float fy = (m0 + 1 < MFEAT) ? sy + eps_add : 0.f;
    g_ctf[((size_t)bh * 72 + e) * 160 + t] = packh2(fx, fy);

    float part = fx + fy;
    #pragma unroll
    for (int off = 16; off; off >>= 1) part += __shfl_xor_sync(0xffffffffu, part, off);
    if ((t & 31) == 0) red[t >> 5] = part;
    __syncthreads();
    if (t == 0) g_ctxsum[bh * 72 + e] = red[0] + red[1] + red[2] + red[3] + red[4];
}

// ---------------------------------------------------------------------------
// out_fused: cp.async double-buffered; GEMM1 = q(fp16 split) @ proj(single fp16),
// 2-term; GEMM2 fp16 single; last-chunk specialization.
// ---------------------------------------------------------------------------
#define OQ_H 0
#define OQ_L 18432
#define OPB  36864           // 2 bufs x 9216 (single fp16 proj)
#define OCB  55296           // 2 bufs x 10368
#define O_DG 76032
#define O_SZ 76544

__global__ void __launch_bounds__(256, 2) out_fused(const float* __restrict__ q_in,
                                                    float* __restrict__ out) {
    extern __shared__ char smem[];
    uint32_t sb = smem_u32(smem);
    int tid = threadIdx.x, w = tid >> 5, lane = tid & 31;
    int bh = blockIdx.y, nt = blockIdx.x;
    const float* qb = q_in + ((size_t)bh * NSEQ + nt * 128) * DDIM;

    for (int i = tid; i < 128 * 32; i += 256) {
        int r = i >> 5, p = i & 31;
        float2 v = *(const float2*)(qb + r * 64 + 2 * p);
        uint32_t hi, lo; split2h(DNORM * v.x, DNORM * v.y, hi, lo);
        *(uint32_t*)(smem + OQ_H + r * 144 + 4 * p) = hi;
        *(uint32_t*)(smem + OQ_L + r * 144 + 4 * p) = lo;
    }
    if (tid < 128) {
        float s = 0.f;
        #pragma unroll
        for (int d = 0; d < DDIM; d++) { float x = qb[tid * 64 + d]; s += x * x; }
        ((float*)(smem + O_DG))[tid] = 0.0625f * s;
    }
    // prologue: stage chunk 0
    {
        uint32_t opb = sb + OPB, ocb = sb + OCB;
        for (int i = tid; i < 512; i += 256) {
            int r = i >> 3, cc = i & 7;
            cp16(opb + r * 144 + 16 * cc, g_pjf + (size_t)r * 32 + 4 * cc);
        }
        for (int i = tid; i < 576; i += 256) {
            int r = i >> 3, cc = i & 7;
            cp16(ocb + r * 144 + 16 * cc, g_ctf + ((size_t)bh * 72 + r) * 160 + 4 * cc);
        }
        CP_COMMIT();
    }

    int arow = lane & 15, koff = (lane >> 4) * 16;
    int br7 = lane & 7, bk8 = ((lane >> 3) & 1) * 16;
    int mh16 = (lane >> 4) & 1;
    int qrow = lane >> 2, qcol2 = 2 * (lane & 3);
    int m0 = 16 * w;
    float M0 = NEGINF, M1 = NEGINF;
    float dg0 = 0.f, dg1 = 0.f;

    float accO[9][4];
    #pragma unroll
    for (int n = 0; n < 9; n++)
        #pragma unroll
        for (int x = 0; x < 4; x++) accO[n][x] = 0.f;

    #pragma unroll 1
    for (int ch = 0; ch < 5; ch++) {
        CP_WAIT0();
        __syncthreads();
        if (ch == 0) {
            dg0 = ((float*)(smem + O_DG))[m0 + qrow];
            dg1 = ((float*)(smem + O_DG))[m0 + qrow + 8];
        }
        if (ch + 1 < 5) {
            uint32_t opb = sb + OPB + ((ch + 1) & 1) * 9216;
            uint32_t ocb = sb + OCB + ((ch + 1) & 1) * 10368;
            for (int i = tid; i < 512; i += 256) {
                int r = i >> 3, cc = i & 7;
                cp16(opb + r * 144 + 16 * cc, g_pjf + (size_t)((ch + 1) * 64 + r) * 32 + 4 * cc);
            }
            for (int i = tid; i < 576; i += 256) {
                int r = i >> 3, cc = i & 7;
                cp16(ocb + r * 144 + 16 * cc, g_ctf + ((size_t)bh * 72 + r) * 160 + 32 * (ch + 1) + 4 * cc);
            }
            CP_COMMIT();
        }

        uint32_t opb = sb + OPB + (ch & 1) * 9216;
        uint32_t ocb = sb + OCB + (ch & 1) * 10368;

        if (ch < 4) {
            float a1[8][4];
            #pragma unroll
            for (int n = 0; n < 8; n++)
                #pragma unroll
                for (int x = 0; x < 4; x++) a1[n][x] = 0.f;
            #pragma unroll
            for (int kt = 0; kt < 4; kt++) {
                uint32_t ah[4], al[4];
                uint32_t a = sb + OQ_H + (uint32_t)(m0 + arow) * 144 + kt * 32 + koff;
                ldsm_x4(ah, a);
                ldsm_x4(al, a + (OQ_L - OQ_H));
                uint32_t bp[8][2];
                #pragma unroll
                for (int np = 0; np < 4; np++) {
                    uint32_t nrow = (uint32_t)(8 * (2 * np + mh16) + br7);
                    ldsm_x4(&bp[2 * np][0], opb + nrow * 144 + kt * 32 + bk8);
                }
                #pragma unroll
                for (int n = 0; n < 8; n++) {
                    mma_f16(a1[n], ah, bp[n]);
                    mma_f16(a1[n], al, bp[n]);
                }
            }

            float lm0 = NEGINF, lm1 = NEGINF;
            #pragma unroll
            for (int n = 0; n < 8; n++) {
                lm0 = fmaxf(lm0, fmaxf(a1[n][0], a1[n][1]));
                lm1 = fmaxf(lm1, fmaxf(a1[n][2], a1[n][3]));
            }
            lm0 = fmaxf(lm0, __shfl_xor_sync(0xffffffffu, lm0, 1));
            lm0 = fmaxf(lm0, __shfl_xor_sync(0xffffffffu, lm0, 2));
            lm1 = fmaxf(lm1, __shfl_xor_sync(0xffffffffu, lm1, 1));
            lm1 = fmaxf(lm1, __shfl_xor_sync(0xffffffffu, lm1, 2));
            float Mn0 = fmaxf(M0, lm0), Mn1 = fmaxf(M1, lm1);
            float f0 = __expf(M0 - Mn0), f1 = __expf(M1 - Mn1);
            M0 = Mn0; M1 = Mn1;
            float off0 = dg0 + Mn0, off1 = dg1 + Mn1;
            #pragma unroll
            for (int n = 0; n < 9; n++) {
                accO[n][0] *= f0; accO[n][1] *= f0;
                accO[n][2] *= f1; accO[n][3] *= f1;
            }

            #pragma unroll
            for (int kt2 = 0; kt2 < 4; kt2++) {
                int u = 2 * kt2, vt = u + 1;
                uint32_t qa[4];
                qa[0] = packh2(RATIO_C * __expf(a1[u][0] - off0), RATIO_C * __expf(a1[u][1] - off0));
                qa[2] = packh2(RATIO_C * __expf(a1[vt][0] - off0), RATIO_C * __expf(a1[vt][1] - off0));
                qa[1] = packh2(RATIO_C * __expf(a1[u][2] - off1), RATIO_C * __expf(a1[u][3] - off1));
                qa[3] = packh2(RATIO_C * __expf(a1[vt][2] - off1), RATIO_C * __expf(a1[vt][3] - off1));
                uint32_t cbh[9][2];
                #pragma unroll
                for (int np = 0; np < 4; np++) {
                    uint32_t nrow = (uint32_t)(8 * (2 * np + mh16) + br7);
                    ldsm_x4(&cbh[2 * np][0], ocb + nrow * 144 + kt2 * 32 + bk8);
                }
                ldsm_x2(cbh[8], ocb + (uint32_t)(64 + br7) * 144 + kt2 * 32 + bk8);
                #pragma unroll
                for (int n = 0; n < 9; n++)
                    mma_f16(accO[n], qa, cbh[n]);
            }
        } else {
            // last chunk (m 256..319, valid < 266): 2 n-tiles, kt2=0 only
            float a1[2][4];
            #pragma unroll
            for (int n = 0; n < 2; n++)
                #pragma unroll
                for (int x = 0; x < 4; x++) a1[n][x] = 0.f;
            #pragma unroll
            for (int kt = 0; kt < 4; kt++) {
                uint32_t ah[4], al[4];
                uint32_t a = sb + OQ_H + (uint32_t)(m0 + arow) * 144 + kt * 32 + koff;
                ldsm_x4(ah, a);
                ldsm_x4(al, a + (OQ_L - OQ_H));
                uint32_t bp[2][2];
                uint32_t nrow = (uint32_t)(8 * mh16 + br7);
                ldsm_x4(&bp[0][0], opb + nrow * 144 + kt * 32 + bk8);
                #pragma unroll
                for (int n = 0; n < 2; n++) {
                    mma_f16(a1[n], ah, bp[n]);
                    mma_f16(a1[n], al, bp[n]);
                }
            }

            float lm0 = NEGINF, lm1 = NEGINF;
            #pragma unroll
            for (int n = 0; n < 2; n++) {
                int gm = 256 + 8 * n + qcol2;
                if (gm < MFEAT)     { lm0 = fmaxf(lm0, a1[n][0]); lm1 = fmaxf(lm1, a1[n][2]); }
                if (gm + 1 < MFEAT) { lm0 = fmaxf(lm0, a1[n][1]); lm1 = fmaxf(lm1, a1[n][3]); }
            }
            lm0 = fmaxf(lm0, __shfl_xor_sync(0xffffffffu, lm0, 1));
            lm0 = fmaxf(lm0, __shfl_xor_sync(0xffffffffu, lm0, 2));
            lm1 = fmaxf(lm1, __shfl_xor_sync(0xffffffffu, lm1, 1));
            lm1 = fmaxf(lm1, __shfl_xor_sync(0xffffffffu, lm1, 2));
            float Mn0 = fmaxf(M0, lm0), Mn1 = fmaxf(M1, lm1);
            float f0 = __expf(M0 - Mn0), f1 = __expf(M1 - Mn1);
            M0 = Mn0; M1 = Mn1;
            float off0 = dg0 + Mn0, off1 = dg1 + Mn1;
            #pragma unroll
            for (int n = 0; n < 9; n++) {
                accO[n][0] *= f0; accO[n][1] *= f0;
                accO[n][2] *= f1; accO[n][3] *= f1;
            }

            int gmu = 256 + qcol2, gmv = 264 + qcol2;
            uint32_t qa[4];
            {
                float a0 = (gmu     < MFEAT) ? RATIO_C * __expf(a1[0][0] - off0) : 0.f;
                float a1v = (gmu + 1 < MFEAT) ? RATIO_C * __expf(a1[0][1] - off0) : 0.f;
                float a2 = (gmv     < MFEAT) ? RATIO_C * __expf(a1[1][0] - off0) : 0.f;
                float a3 = (gmv + 1 < MFEAT) ? RATIO_C * __expf(a1[1][1] - off0) : 0.f;
                qa[0] = packh2(a0, a1v); qa[2] = packh2(a2, a3);
            }
            {
                float a0 = (gmu     < MFEAT) ? RATIO_C * __expf(a1[0][2] - off1) : 0.f;
                float a1v = (gmu + 1 < MFEAT) ? RATIO_C * __expf(a1[0][3] - off1) : 0.f;
                float a2 = (gmv     < MFEAT) ? RATIO_C * __expf(a1[1][2] - off1) : 0.f;
                float a3 = (gmv + 1 < MFEAT) ? RATIO_C * __expf(a1[1][3] - off1) : 0.f;
                qa[1] = packh2(a0, a1v); qa[3] = packh2(a2, a3);
            }
            uint32_t cbh[9][2];
            #pragma unroll
            for (int np = 0; np < 4; np++) {
                uint32_t nrow = (uint32_t)(8 * (2 * np + mh16) + br7);
                ldsm_x4(&cbh[2 * np][0], ocb + nrow * 144 + bk8);
            }
            ldsm_x2(cbh[8], ocb + (uint32_t)(64 + br7) * 144 + bk8);
            #pragma unroll
            for (int n = 0; n < 9; n++)
                mma_f16(accO[n], qa, cbh[n]);
        }
    }

    #pragma unroll
    for (int n = 0; n < 9; n++) {
        int col = 8 * n + qcol2;
        float cs0 = g_ctxsum[bh * 72 + col];
        float cs1 = g_ctxsum[bh * 72 + col + 1];
        accO[n][0] += REPS_C * cs0; accO[n][1] += REPS_C * cs1;
        accO[n][2] += REPS_C * cs0; accO[n][3] += REPS_C * cs1;
    }
    float d0 = __shfl_sync(0xffffffffu, accO[8][0], lane & ~3);
    float d1 = __shfl_sync(0xffffffffu, accO[8][2], lane & ~3);
    float i0 = 1.0f / d0, i1 = 1.0f / d1;
    int r0g = nt * 128 + m0 + qrow;
    float* ob = out + (size_t)bh * NSEQ * DDIM;
    #pragma unroll
    for (int n = 0; n < 8; n++) {
        int col = 8 * n + qcol2;
        *(float2*)(ob + (size_t)r0g * DDIM + col) = make_float2(i0 * accO[n][0], i0 * accO[n][1]);
        *(float2*)(ob + (size_t)(r0g + 8) * DDIM + col) = make_float2(i1 * accO[n][2], i1 * accO[n][3]);
    }
}

// ---------------------------------------------------------------------------
extern "C" void kernel_launch(void* const* d_in, const int* in_sizes, int n_in,
                              void* d_out, int out_size) {
    const float* q    = (const float*)d_in[0];
    const float* k    = (const float*)d_in[1];
    const float* v    = (const float*)d_in[2];
    const float* proj = (const float*)d_in[3];
    float* out = (float*)d_out;

    cudaFuncSetAttribute(ctx_fused, cudaFuncAttributeMaxDynamicSharedMemorySize, CX_SZ);
    cudaFuncSetAttribute(out_fused, cudaFuncAttributeMaxDynamicSharedMemorySize, O_SZ);

    init_kernel<<<1, 32>>>();
    prep_proj<<<48, 256>>>(proj);
    ctx_fused<<<dim3(3 * KSPL, BH), 256, CX_SZ>>>(k, v, proj);
    convert_kernel<<<dim3(72, BH), 160>>>();
    out_fused<<<dim3(NT, BH), 256, O_SZ>>>(q, out);
}

// round 16
// speedup vs baseline: 1.3032x; 1.3032x over previous
#include <cuda_runtime.h>
#include <cuda_bf16.h>
#include <cuda_fp16.h>
#include <cstdint>

#define BH    32
#define NSEQ  4096
#define DDIM  64
#define MFEAT 266
#define MP    320
#define NT    32
#define KSPL  16
#define KSEG  (NSEQ / KSPL)

#define DNORM   0.35355339059327373f
#define RATIO_C 0.061313933948496576f
#define REPS_C  6.1313933948496576e-06f   // ratio * 1e-4
#define NEGINF  -1.0e30f

// ---------------- global scratch (static; no cudaMalloc) --------------------
__device__ float        g_ctxS[(size_t)KSPL * BH * 72 * MP];   // K-split ctx^T partials
__device__ float        g_ctxM[KSPL * BH * 3];                 // per (slab, mtile) stabilizer
__device__ float        g_ctxsum[BH * 72];                     // sum_m ctx[m,e]
__device__ uint32_t     g_ctf[(size_t)BH * 72 * 160];          // ctx^T fp16 pairs
__device__ uint32_t     g_pjf[384 * 32];                       // proj fp16 pairs (padded rows)
__device__ unsigned int g_kmax_enc;

__device__ __forceinline__ unsigned int enc_f(float f) {
    unsigned int u = __float_as_uint(f);
    return (u & 0x80000000u) ? ~u : (u | 0x80000000u);
}
__device__ __forceinline__ float dec_f(unsigned int k) {
    return (k & 0x80000000u) ? __uint_as_float(k & 0x7fffffffu) : __uint_as_float(~k);
}
__device__ __forceinline__ uint32_t smem_u32(const void* p) {
    uint32_t a;
    asm("{ .reg .u64 t; cvta.to.shared.u64 t, %1; cvt.u32.u64 %0, t; }" : "=r"(a) : "l"(p));
    return a;
}
__device__ __forceinline__ uint32_t packh2(float a, float b) {
    __half2 t = __floats2half2_rn(a, b);
    return reinterpret_cast<uint32_t&>(t);
}
// bf16 hi/lo split (ctx GEMM1 path, proven)
__device__ __forceinline__ void split2(float a, float b, uint32_t& hi, uint32_t& lo) {
    __nv_bfloat16 ha = __float2bfloat16_rn(a), hb = __float2bfloat16_rn(b);
    float ra = a - __bfloat162float(ha), rb = b - __bfloat162float(hb);
    __nv_bfloat162 H; H.x = ha; H.y = hb;
    hi = reinterpret_cast<uint32_t&>(H);
    __nv_bfloat162 L; L.x = __float2bfloat16_rn(ra); L.y = __float2bfloat16_rn(rb);
    lo = reinterpret_cast<uint32_t&>(L);
}
// fp16 hi/lo split (out GEMM1 path)
__device__ __forceinline__ void split2h(float a, float b, uint32_t& hi, uint32_t& lo) {
    __half ha = __float2half_rn(a), hb = __float2half_rn(b);
    float ra = a - __half2float(ha), rb = b - __half2float(hb);
    __half2 H; H.x = ha; H.y = hb;
    hi = reinterpret_cast<uint32_t&>(H);
    lo = packh2(ra, rb);
}

// ---------------- cp.async helpers ------------------------------------------
__device__ __forceinline__ void cp16(uint32_t saddr, const void* gptr) {
    asm volatile("cp.async.cg.shared.global [%0], [%1], 16;" :: "r"(saddr), "l"(gptr));
}
#define CP_COMMIT() asm volatile("cp.async.commit_group;" ::: "memory")
#define CP_WAIT0()  asm volatile("cp.async.wait_group 0;" ::: "memory")

// ---------------- mma.sync + ldmatrix helpers -------------------------------
__device__ __forceinline__ void ldsm_x4(uint32_t* r, uint32_t addr) {
    asm volatile("ldmatrix.sync.aligned.m8n8.x4.shared.b16 {%0,%1,%2,%3}, [%4];"
        : "=r"(r[0]), "=r"(r[1]), "=r"(r[2]), "=r"(r[3]) : "r"(addr));
}
__device__ __forceinline__ void ldsm_x2(uint32_t* r, uint32_t addr) {
    asm volatile("ldmatrix.sync.aligned.m8n8.x2.shared.b16 {%0,%1}, [%2];"
        : "=r"(r[0]), "=r"(r[1]) : "r"(addr));
}
__device__ __forceinline__ void ldsm_x4t(uint32_t* r, uint32_t addr) {
    asm volatile("ldmatrix.sync.aligned.m8n8.x4.trans.shared.b16 {%0,%1,%2,%3}, [%4];"
        : "=r"(r[0]), "=r"(r[1]), "=r"(r[2]), "=r"(r[3]) : "r"(addr));
}
__device__ __forceinline__ void ldsm_x2t(uint32_t* r, uint32_t addr) {
    asm volatile("ldmatrix.sync.aligned.m8n8.x2.trans.shared.b16 {%0,%1}, [%2];"
        : "=r"(r[0]), "=r"(r[1]) : "r"(addr));
}
__device__ __forceinline__ void mma_bf16(float* c, const uint32_t* a, const uint32_t* b) {
    asm volatile("mma.sync.aligned.m16n8k16.row.col.f32.bf16.bf16.f32 "
        "{%0,%1,%2,%3}, {%4,%5,%6,%7}, {%8,%9}, {%0,%1,%2,%3};"
        : "+f"(c[0]), "+f"(c[1]), "+f"(c[2]), "+f"(c[3])
        : "r"(a[0]), "r"(a[1]), "r"(a[2]), "r"(a[3]), "r"(b[0]), "r"(b[1]));
}
__device__ __forceinline__ void mma_f16(float* c, const uint32_t* a, const uint32_t* b) {
    asm volatile("mma.sync.aligned.m16n8k16.row.col.f32.f16.f16.f32 "
        "{%0,%1,%2,%3}, {%4,%5,%6,%7}, {%8,%9}, {%0,%1,%2,%3};"
        : "+f"(c[0]), "+f"(c[1]), "+f"(c[2]), "+f"(c[3])
        : "r"(a[0]), "r"(a[1]), "r"(a[2]), "r"(a[3]), "r"(b[0]), "r"(b[1]));
}

// ---------------------------------------------------------------------------
__global__ void init_kernel() {
    if (threadIdx.x == 0 && blockIdx.x == 0) g_kmax_enc = 0u;
}

// prep_proj: proj -> single fp16 pairs, rows padded to 384 with zeros.
__global__ void prep_proj(const float* __restrict__ proj) {
    int i = blockIdx.x * blockDim.x + threadIdx.x;
    if (i >= 384 * 32) return;
    int r = i >> 5, p = i & 31;
    float2 v = (r < MFEAT) ? *(const float2*)(proj + r * 64 + 2 * p) : make_float2(0.f, 0.f);
    g_pjf[i] = packh2(v.x, v.y);
}

// ---------------------------------------------------------------------------
// ctx_fused: VERBATIM R14 (best-known): bf16 3-term GEMM1, smem-based diag,
// fp16 single-product GEMM2. grid (3*KSPL, BH), block 256, 2 CTAs/SM.
// ---------------------------------------------------------------------------
#define CP_H 0
#define CP_L 18432
#define CK_H 36864
#define CK_L 46080
#define CW_  55296
#define CD_  66560
#define C_MX 66816
#define CX_SZ 66880

__global__ void __launch_bounds__(256, 2) ctx_fused(const float* __restrict__ k_in,
                                                    const float* __restrict__ v_in,
                                                    const float* __restrict__ proj) {
    extern __shared__ char smem[];
    uint32_t sb = smem_u32(smem);
    int tid = threadIdx.x, w = tid >> 5, lane = tid & 31;
    int bh = blockIdx.y, mtile = blockIdx.x % 3, ks = blockIdx.x / 3;

    int arow = lane & 15, koff = (lane >> 4) * 16;
    int br7 = lane & 7, bk8 = ((lane >> 3) & 1) * 16;
    int mh16 = (lane >> 4) & 1;
    int krb  = (lane & 7) + 8 * ((lane >> 3) & 1);
    int qrow = lane >> 2, qcol2 = 2 * (lane & 3);
    int tileid = 8 * mtile + w;
    bool wvalid = tileid <= 16;
    int mr0 = mtile * 128 + 16 * w + qrow;

    for (int i = tid; i < 128 * 32; i += 256) {
        int r = i >> 5, p = i & 31;
        int m = mtile * 128 + r;
        float2 v = (m < MFEAT) ? *(const float2*)(proj + m * 64 + 2 * p) : make_float2(0.f, 0.f);
        uint32_t hi, lo; split2(v.x, v.y, hi, lo);
        *(uint32_t*)(smem + CP_H + r * 144 + 4 * p) = hi;
        *(uint32_t*)(smem + CP_L + r * 144 + 4 * p) = lo;
    }

    float accC[9][4];
    #pragma unroll
    for (int n = 0; n < 9; n++)
        #pragma unroll
        for (int x = 0; x < 4; x++) accC[n][x] = 0.f;
    float Mold = NEGINF;

    #pragma unroll 1
    for (int c = 0; c < KSEG / 64; c++) {
        int n0 = ks * KSEG + c * 64;
        __syncthreads();
        const float* kb = k_in + ((size_t)bh * NSEQ + n0) * DDIM;
        for (int i = tid; i < 64 * 32; i += 256) {
            int r = i >> 5, p = i & 31;
            float2 v = *(const float2*)(kb + r * 64 + 2 * p);
            uint32_t hi, lo; split2(DNORM * v.x, DNORM * v.y, hi, lo);
            *(uint32_t*)(smem + CK_H + r * 144 + 4 * p) = hi;
            *(uint32_t*)(smem + CK_L + r * 144 + 4 * p) = lo;
        }
        const float* vb = v_in + ((size_t)bh * NSEQ + n0) * DDIM;
        for (int i = tid; i < 64 * 36; i += 256) {
            int r = i / 36, p = i % 36;
            int e = 2 * p;
            float2 wv;
            if (e < 64)       wv = *(const float2*)(vb + r * 64 + e);
            else if (e == 64) wv = make_float2(1.f, 0.f);
            else              wv = make_float2(0.f, 0.f);
            *(uint32_t*)(smem + CW_ + r * 176 + 4 * p) = packh2(wv.x, wv.y);
        }
        __syncthreads();

        if (tid < 64) {
            float s = 0.f;
            #pragma unroll
            for (int p = 0; p < 32; p++) {
                uint32_t hu = *(uint32_t*)(smem + CK_H + tid * 144 + 4 * p);
                uint32_t lu = *(uint32_t*)(smem + CK_L + tid * 144 + 4 * p);
                __nv_bfloat162 hb2 = reinterpret_cast<__nv_bfloat162&>(hu);
                __nv_bfloat162 lb2 = reinterpret_cast<__nv_bfloat162&>(lu);
                float x0 = __bfloat162float(hb2.x) + __bfloat162float(lb2.x);
                float x1 = __bfloat162float(hb2.y) + __bfloat162float(lb2.y);
                s += x0 * x0 + x1 * x1;
            }
            ((float*)(smem + CD_))[tid] = 0.5f * s;
        }
        __syncthreads();

        float c1[8][4];
        #pragma unroll
        for (int n = 0; n < 8; n++)
            #pragma unroll
            for (int x = 0; x < 4; x++) c1[n][x] = 0.f;
        if (wvalid) {
            #pragma unroll
            for (int kt = 0; kt < 4; kt++) {
                uint32_t aph[4], apl[4];
                uint32_t a = sb + CP_H + (uint32_t)(16 * w + arow) * 144 + kt * 32 + koff;
                ldsm_x4(aph, a);
                ldsm_x4(apl, a + (CP_L - CP_H));
                uint32_t bkh[8][2], bkl[8][2];
                #pragma unroll
                for (int np = 0; np < 4; np++) {
                    uint32_t nrow = (uint32_t)(8 * (2 * np + mh16) + br7);
                    uint32_t b = sb + CK_H + nrow * 144 + kt * 32 + bk8;
                    ldsm_x4(&bkh[2 * np][0], b);
                    ldsm_x4(&bkl[2 * np][0], b + (CK_L - CK_H));
                }
                #pragma unroll
                for (int n = 0; n < 8; n++) {
                    mma_bf16(c1[n], aph, bkh[n]);
                    mma_bf16(c1[n], aph, bkl[n]);
                    mma_bf16(c1[n], apl, bkh[n]);
                }
            }
        }

        bool v0 = wvalid && (mr0 < MFEAT), v1 = wvalid && (mr0 + 8 < MFEAT);
        float lm = NEGINF;
        #pragma unroll
        for (int n = 0; n < 8; n++) {
            if (v0) lm = fmaxf(lm, fmaxf(c1[n][0], c1[n][1]));
            if (v1) lm = fmaxf(lm, fmaxf(c1[n][2], c1[n][3]));
        }
        #pragma unroll
        for (int off = 16; off; off >>= 1) lm = fmaxf(lm, __shfl_xor_sync(0xffffffffu, lm, off));
        if (lane == 0) ((float*)(smem + C_MX))[w] = lm;
        __syncthreads();
        float bmax = NEGINF;
        #pragma unroll
        for (int i = 0; i < 8; i++) bmax = fmaxf(bmax, ((float*)(smem + C_MX))[i]);
        float Mnew = fmaxf(Mold, bmax);

        if (wvalid) {
            float factor = __expf(Mold - Mnew);
            float f0 = (mr0 == MFEAT) ? 1.f : factor;
            float f1 = (mr0 + 8 == MFEAT) ? 1.f : factor;
            #pragma unroll
            for (int n = 0; n < 9; n++) {
                accC[n][0] *= f0; accC[n][1] *= f0;
                accC[n][2] *= f1; accC[n][3] *= f1;
            }

            float* dg = (float*)(smem + CD_);
            #pragma unroll
            for (int kt2 = 0; kt2 < 4; kt2++) {
                int u = 2 * kt2, vt = u + 1;
                int ncol = 16 * kt2 + qcol2;
                float dgu0 = dg[ncol],     dgu1 = dg[ncol + 1];
                float dgv0 = dg[ncol + 8], dgv1 = dg[ncol + 9];
                uint32_t qa[4];
                {
                    float a0, a1, a2, a3;
                    if (mr0 < MFEAT) {
                        a0 = RATIO_C * __expf(c1[u][0] - dgu0 - Mnew);
                        a1 = RATIO_C * __expf(c1[u][1] - dgu1 - Mnew);
                        a2 = RATIO_C * __expf(c1[vt][0] - dgv0 - Mnew);
                        a3 = RATIO_C * __expf(c1[vt][1] - dgv1 - Mnew);
                    } else if (mr0 == MFEAT) { a0 = a1 = a2 = a3 = 1.f; }
                    else { a0 = a1 = a2 = a3 = 0.f; }
                    qa[0] = packh2(a0, a1); qa[2] = packh2(a2, a3);
                }
                {
                    int m1 = mr0 + 8;
                    float a0, a1, a2, a3;
                    if (m1 < MFEAT) {
                        a0 = RATIO_C * __expf(c1[u][2] - dgu0 - Mnew);
                        a1 = RATIO_C * __expf(c1[u][3] - dgu1 - Mnew);
                        a2 = RATIO_C * __expf(c1[vt][2] - dgv0 - Mnew);
                        a3 = RATIO_C * __expf(c1[vt][3] - dgv1 - Mnew);
                    } else if (m1 == MFEAT) { a0 = a1 = a2 = a3 = 1.f; }
                    else { a0 = a1 = a2 = a3 = 0.f; }
                    qa[1] = packh2(a0, a1); qa[3] = packh2(a2, a3);
                }
                uint32_t bwh[9][2];
                uint32_t wrow = sb + CW_ + (uint32_t)(kt2 * 16 + krb) * 176;
                #pragma unroll
                for (int np = 0; np < 4; np++)
                    ldsm_x4t(&bwh[2 * np][0], wrow + 16 * (uint32_t)(2 * np + mh16));
                ldsm_x2t(bwh[8], wrow + 128);
                #pragma unroll
                for (int nE = 0; nE < 9; nE++)
                    mma_f16(accC[nE], qa, bwh[nE]);
            }
        }
        Mold = Mnew;
    }

    if (wvalid) {
        float* slab = g_ctxS + ((size_t)(ks * BH + bh)) * 72 * MP;
        #pragma unroll
        for (int nE = 0; nE < 9; nE++) {
            int e = 8 * nE + qcol2;
            slab[(size_t)e * MP + mr0]           = accC[nE][0];
            slab[(size_t)(e + 1) * MP + mr0]     = accC[nE][1];
            slab[(size_t)e * MP + mr0 + 8]       = accC[nE][2];
            slab[(size_t)(e + 1) * MP + mr0 + 8] = accC[nE][3];
        }
    }
    if (tid == 0) {
        g_ctxM[(ks * BH + bh) * 3 + mtile] = Mold;
        atomicMax(&g_kmax_enc, enc_f(Mold));
    }
}

// ---------------------------------------------------------------------------
// convert: VERBATIM R14.
// ---------------------------------------------------------------------------
__global__ void __launch_bounds__(160) convert_kernel() {
    __shared__ float sc[KSPL * 3];
    __shared__ float vs_sh;
    __shared__ float red[5];
    int e = blockIdx.x, bh = blockIdx.y, t = threadIdx.x;
    float G = dec_f(g_kmax_enc);
    if (t < KSPL * 3) sc[t] = __expf(g_ctxM[(t / 3 * BH + bh) * 3 + (t % 3)] - G);
    if (t == 0) {
        float v = 0.f;
        #pragma unroll
        for (int ks = 0; ks < KSPL; ks++)
            v += g_ctxS[(((size_t)(ks * BH + bh)) * 72 + e) * MP + MFEAT];
        vs_sh = v;
    }
    __syncthreads();

    int mt = t >> 6;
    int m0 = 2 * t;
    float sx = 0.f, sy = 0.f;
    if (m0 < 272) {
        #pragma unroll
        for (int ks = 0; ks < KSPL; ks++) {
            float2 vv = *(const float2*)(g_ctxS + (((size_t)(ks * BH + bh)) * 72 + e) * MP + m0);
            float s = sc[ks * 3 + mt];
            sx += s * vv.x; sy += s * vv.y;
        }
    }
    float eps_add = REPS_C * vs_sh;
    float fx = (m0     < MFEAT) ? sx + eps_add : 0.f;
    float fy = (m0 + 1 < MFEAT) ? sy + eps_add : 0.f;
    g_ctf[((size_t)bh * 72 + e) * 160 + t] = packh2(fx, fy);

    float part = fx + fy;
    #pragma unroll
    for (int off = 16; off; off >>= 1) part += __shfl_xor_sync(0xffffffffu, part, off);
    if ((t & 31) == 0) red[t >> 5] = part;
    __syncthreads();
    if (t == 0) g_ctxsum[bh * 72 + e] = red[0] + red[1] + red[2] + red[3] + red[4];
}

// ---------------------------------------------------------------------------
// out_fused: R14 pipeline + fp16 2-term GEMM1 (q split fp16, proj single fp16).
// ---------------------------------------------------------------------------
#define OQ_H 0
#define OQ_L 18432
#define OPB  36864           // 2 bufs x 9216 (single fp16 proj)
#define OCB  55296           // 2 bufs x 10368
#define O_DG 76032
#define O_SZ 76544

__global__ void __launch_bounds__(256, 2) out_fused(const float* __restrict__ q_in,
                                                    float* __restrict__ out) {
    extern __shared__ char smem[];
    uint32_t sb = smem_u32(smem);
    int tid = threadIdx.x, w = tid >> 5, lane = tid & 31;
    int bh = blockIdx.y, nt = blockIdx.x;
    const float* qb = q_in + ((size_t)bh * NSEQ + nt * 128) * DDIM;

    for (int i = tid; i < 128 * 32; i += 256) {
        int r = i >> 5, p = i & 31;
        float2 v = *(const float2*)(qb + r * 64 + 2 * p);
        uint32_t hi, lo; split2h(DNORM * v.x, DNORM * v.y, hi, lo);
        *(uint32_t*)(smem + OQ_H + r * 144 + 4 * p) = hi;
        *(uint32_t*)(smem + OQ_L + r * 144 + 4 * p) = lo;
    }
    if (tid < 128) {
        float s = 0.f;
        #pragma unroll
        for (int d = 0; d < DDIM; d++) { float x = qb[tid * 64 + d]; s += x * x; }
        ((float*)(smem + O_DG))[tid] = 0.0625f * s;
    }
    // prologue: stage chunk 0
    {
        uint32_t opb = sb + OPB, ocb = sb + OCB;
        for (int i = tid; i < 512; i += 256) {
            int r = i >> 3, cc = i & 7;
            cp16(opb + r * 144 + 16 * cc, g_pjf + (size_t)r * 32 + 4 * cc);
        }
        for (int i = tid; i < 576; i += 256) {
            int r = i >> 3, cc = i & 7;
            cp16(ocb + r * 144 + 16 * cc, g_ctf + ((size_t)bh * 72 + r) * 160 + 4 * cc);
        }
        CP_COMMIT();
    }

    int arow = lane & 15, koff = (lane >> 4) * 16;
    int br7 = lane & 7, bk8 = ((lane >> 3) & 1) * 16;
    int mh16 = (lane >> 4) & 1;
    int qrow = lane >> 2, qcol2 = 2 * (lane & 3);
    int m0 = 16 * w;
    float M0 = NEGINF, M1 = NEGINF;
    float dg0 = 0.f, dg1 = 0.f;

    float accO[9][4];
    #pragma unroll
    for (int n = 0; n < 9; n++)
        #pragma unroll
        for (int x = 0; x < 4; x++) accO[n][x] = 0.f;

    #pragma unroll 1
    for (int ch = 0; ch < 5; ch++) {
        CP_WAIT0();
        __syncthreads();
        if (ch == 0) {
            dg0 = ((float*)(smem + O_DG))[m0 + qrow];
            dg1 = ((float*)(smem + O_DG))[m0 + qrow + 8];
        }
        if (ch + 1 < 5) {
            uint32_t opb = sb + OPB + ((ch + 1) & 1) * 9216;
            uint32_t ocb = sb + OCB + ((ch + 1) & 1) * 10368;
            for (int i = tid; i < 512; i += 256) {
                int r = i >> 3, cc = i & 7;
                cp16(opb + r * 144 + 16 * cc, g_pjf + (size_t)((ch + 1) * 64 + r) * 32 + 4 * cc);
            }
            for (int i = tid; i < 576; i += 256) {
                int r = i >> 3, cc = i & 7;
                cp16(ocb + r * 144 + 16 * cc, g_ctf + ((size_t)bh * 72 + r) * 160 + 32 * (ch + 1) + 4 * cc);
            }
            CP_COMMIT();
        }

        uint32_t opb = sb + OPB + (ch & 1) * 9216;
        uint32_t ocb = sb + OCB + (ch & 1) * 10368;

        if (ch < 4) {
            float a1[8][4];
            #pragma unroll
            for (int n = 0; n < 8; n++)
                #pragma unroll
                for (int x = 0; x < 4; x++) a1[n][x] = 0.f;
            #pragma unroll
            for (int kt = 0; kt < 4; kt++) {
                uint32_t ah[4], al[4];
                uint32_t a = sb + OQ_H + (uint32_t)(m0 + arow) * 144 + kt * 32 + koff;
                ldsm_x4(ah, a);
                ldsm_x4(al, a + (OQ_L - OQ_H));
                uint32_t bp[8][2];
                #pragma unroll
                for (int np = 0; np < 4; np++) {
                    uint32_t nrow = (uint32_t)(8 * (2 * np + mh16) + br7);
                    ldsm_x4(&bp[2 * np][0], opb + nrow * 144 + kt * 32 + bk8);
                }
                #pragma unroll
                for (int n = 0; n < 8; n++) {
                    mma_f16(a1[n], ah, bp[n]);
                    mma_f16(a1[n], al, bp[n]);
                }
            }

            float lm0 = NEGINF, lm1 = NEGINF;
            #pragma unroll
            for (int n = 0; n < 8; n++) {
                lm0 = fmaxf(lm0, fmaxf(a1[n][0], a1[n][1]));
                lm1 = fmaxf(lm1, fmaxf(a1[n][2], a1[n][3]));
            }
            lm0 = fmaxf(lm0, __shfl_xor_sync(0xffffffffu, lm0, 1));
            lm0 = fmaxf(lm0, __shfl_xor_sync(0xffffffffu, lm0, 2));
            lm1 = fmaxf(lm1, __shfl_xor_sync(0xffffffffu, lm1, 1));
            lm1 = fmaxf(lm1, __shfl_xor_sync(0xffffffffu, lm1, 2));
            float Mn0 = fmaxf(M0, lm0), Mn1 = fmaxf(M1, lm1);
            float f0 = __expf(M0 - Mn0), f1 = __expf(M1 - Mn1);
            M0 = Mn0; M1 = Mn1;
            float off0 = dg0 + Mn0, off1 = dg1 + Mn1;
            #pragma unroll
            for (int n = 0; n < 9; n++) {
                accO[n][0] *= f0; accO[n][1] *= f0;
                accO[n][2] *= f1; accO[n][3] *= f1;
            }

            #pragma unroll
            for (int kt2 = 0; kt2 < 4; kt2++) {
                int u = 2 * kt2, vt = u + 1;
                uint32_t qa[4];
                qa[0] = packh2(RATIO_C * __expf(a1[u][0] - off0), RATIO_C * __expf(a1[u][1] - off0));
                qa[2] = packh2(RATIO_C * __expf(a1[vt][0] - off0), RATIO_C * __expf(a1[vt][1] - off0));
                qa[1] = packh2(RATIO_C * __expf(a1[u][2] - off1), RATIO_C * __expf(a1[u][3] - off1));
                qa[3] = packh2(RATIO_C * __expf(a1[vt][2] - off1), RATIO_C * __expf(a1[vt][3] - off1));
                uint32_t cbh[9][2];
                #pragma unroll
                for (int np = 0; np < 4; np++) {
                    uint32_t nrow = (uint32_t)(8 * (2 * np + mh16) + br7);
                    ldsm_x4(&cbh[2 * np][0], ocb + nrow * 144 + kt2 * 32 + bk8);
                }
                ldsm_x2(cbh[8], ocb + (uint32_t)(64 + br7) * 144 + kt2 * 32 + bk8);
                #pragma unroll
                for (int n = 0; n < 9; n++)
                    mma_f16(accO[n], qa, cbh[n]);
            }
        } else {
            // last chunk (m 256..319, valid < 266): 2 n-tiles, kt2=0 only
            float a1[2][4];
            #pragma unroll
            for (int n = 0; n < 2; n++)
                #pragma unroll
                for (int x = 0; x < 4; x++) a1[n][x] = 0.f;
            #pragma unroll
            for (int kt = 0; kt < 4; kt++) {
                uint32_t ah[4], al[4];
                uint32_t a = sb + OQ_H + (uint32_t)(m0 + arow) * 144 + kt * 32 + koff;
                ldsm_x4(ah, a);
                ldsm_x4(al, a + (OQ_L - OQ_H));
                uint32_t bp[2][2];
                uint32_t nrow = (uint32_t)(8 * mh16 + br7);
                ldsm_x4(&bp[0][0], opb + nrow * 144 + kt * 32 + bk8);
                #pragma unroll
                for (int n = 0; n < 2; n++) {
                    mma_f16(a1[n], ah, bp[n]);
                    mma_f16(a1[n], al, bp[n]);
                }
            }

            float lm0 = NEGINF, lm1 = NEGINF;
            #pragma unroll
            for (int n = 0; n < 2; n++) {
                int gm = 256 + 8 * n + qcol2;
                if (gm < MFEAT)     { lm0 = fmaxf(lm0, a1[n][0]); lm1 = fmaxf(lm1, a1[n][2]); }
                if (gm + 1 < MFEAT) { lm0 = fmaxf(lm0, a1[n][1]); lm1 = fmaxf(lm1, a1[n][3]); }
            }
            lm0 = fmaxf(lm0, __shfl_xor_sync(0xffffffffu, lm0, 1));
            lm0 = fmaxf(lm0, __shfl_xor_sync(0xffffffffu, lm0, 2));
            lm1 = fmaxf(lm1, __shfl_xor_sync(0xffffffffu, lm1, 1));
            lm1 = fmaxf(lm1, __shfl_xor_sync(0xffffffffu, lm1, 2));
            float Mn0 = fmaxf(M0, lm0), Mn1 = fmaxf(M1, lm1);
            float f0 = __expf(M0 - Mn0), f1 = __expf(M1 - Mn1);
            M0 = Mn0; M1 = Mn1;
            float off0 = dg0 + Mn0, off1 = dg1 + Mn1;
            #pragma unroll
            for (int n = 0; n < 9; n++) {
                accO[n][0] *= f0; accO[n][1] *= f0;
                accO[n][2] *= f1; accO[n][3] *= f1;
            }

            int gmu = 256 + qcol2, gmv = 264 + qcol2;
            uint32_t qa[4];
            {
                float a0 = (gmu     < MFEAT) ? RATIO_C * __expf(a1[0][0] - off0) : 0.f;
                float a1v = (gmu + 1 < MFEAT) ? RATIO_C * __expf(a1[0][1] - off0) : 0.f;
                float a2 = (gmv     < MFEAT) ? RATIO_C * __expf(a1[1][0] - off0) : 0.f;
                float a3 = (gmv + 1 < MFEAT) ? RATIO_C * __expf(a1[1][1] - off0) : 0.f;
                qa[0] = packh2(a0, a1v); qa[2] = packh2(a2, a3);
            }
            {
                float a0 = (gmu     < MFEAT) ? RATIO_C * __expf(a1[0][2] - off1) : 0.f;
                float a1v = (gmu + 1 < MFEAT) ? RATIO_C * __expf(a1[0][3] - off1) : 0.f;
                float a2 = (gmv     < MFEAT) ? RATIO_C * __expf(a1[1][2] - off1) : 0.f;
                float a3 = (gmv + 1 < MFEAT) ? RATIO_C * __expf(a1[1][3] - off1) : 0.f;
                qa[1] = packh2(a0, a1v); qa[3] = packh2(a2, a3);
            }
            uint32_t cbh[9][2];
            #pragma unroll
            for (int np = 0; np < 4; np++) {
                uint32_t nrow = (uint32_t)(8 * (2 * np + mh16) + br7);
                ldsm_x4(&cbh[2 * np][0], ocb + nrow * 144 + bk8);
            }
            ldsm_x2(cbh[8], ocb + (uint32_t)(64 + br7) * 144 + bk8);
            #pragma unroll
            for (int n = 0; n < 9; n++)
                mma_f16(accO[n], qa, cbh[n]);
        }
    }

    #pragma unroll
    for (int n = 0; n < 9; n++) {
        int col = 8 * n + qcol2;
        float cs0 = g_ctxsum[bh * 72 + col];
        float cs1 = g_ctxsum[bh * 72 + col + 1];
        accO[n][0] += REPS_C * cs0; accO[n][1] += REPS_C * cs1;
        accO[n][2] += REPS_C * cs0; accO[n][3] += REPS_C * cs1;
    }
    float d0 = __shfl_sync(0xffffffffu, accO[8][0], lane & ~3);
    float d1 = __shfl_sync(0xffffffffu, accO[8][2], lane & ~3);
    float i0 = 1.0f / d0, i1 = 1.0f / d1;
    int r0g = nt * 128 + m0 + qrow;
    float* ob = out + (size_t)bh * NSEQ * DDIM;
    #pragma unroll
    for (int n = 0; n < 8; n++) {
        int col = 8 * n + qcol2;
        *(float2*)(ob + (size_t)r0g * DDIM + col) = make_float2(i0 * accO[n][0], i0 * accO[n][1]);
        *(float2*)(ob + (size_t)(r0g + 8) * DDIM + col) = make_float2(i1 * accO[n][2], i1 * accO[n][3]);
    }
}

// ---------------------------------------------------------------------------
extern "C" void kernel_launch(void* const* d_in, const int* in_sizes, int n_in,
                              void* d_out, int out_size) {
    const float* q    = (const float*)d_in[0];
    const float* k    = (const float*)d_in[1];
    const float* v    = (const float*)d_in[2];
    const float* proj = (const float*)d_in[3];
    float* out = (float*)d_out;

    cudaFuncSetAttribute(ctx_fused, cudaFuncAttributeMaxDynamicSharedMemorySize, CX_SZ);
    cudaFuncSetAttribute(out_fused, cudaFuncAttributeMaxDynamicSharedMemorySize, O_SZ);

    init_kernel<<<1, 32>>>();
    prep_proj<<<48, 256>>>(proj);
    ctx_fused<<<dim3(3 * KSPL, BH), 256, CX_SZ>>>(k, v, proj);
    convert_kernel<<<dim3(72, BH), 160>>>();
    out_fused<<<dim3(NT, BH), 256, O_SZ>>>(q, out);
}

// round 17
// speedup vs baseline: 1.3947x; 1.0702x over previous
#include <cuda_runtime.h>
#include <cuda_bf16.h>
#include <cuda_fp16.h>
#include <cstdint>

#define BH    32
#define NSEQ  4096
#define DDIM  64
#define MFEAT 266
#define MP    320
#define NT    32
#define KSPL  16
#define KSEG  (NSEQ / KSPL)

#define DNORM   0.35355339059327373f
#define RATIO_C 0.061313933948496576f
#define REPS_C  6.1313933948496576e-06f   // ratio * 1e-4
#define NEGINF  -1.0e30f

// ---------------- global scratch (static; no cudaMalloc) --------------------
__device__ float        g_ctxS[(size_t)KSPL * BH * 72 * MP];   // K-split ctx^T partials
__device__ float        g_ctxM[KSPL * BH * 3];                 // per (slab, mtile) stabilizer
__device__ float        g_ctxsum[BH * 72];                     // sum_m ctx[m,e]
__device__ uint32_t     g_ctf[(size_t)BH * 72 * 160];          // ctx^T fp16 pairs
__device__ uint32_t     g_pjf[384 * 32];                       // proj fp16 pairs (padded rows)
__device__ unsigned int g_kmax_enc;

__device__ __forceinline__ unsigned int enc_f(float f) {
    unsigned int u = __float_as_uint(f);
    return (u & 0x80000000u) ? ~u : (u | 0x80000000u);
}
__device__ __forceinline__ float dec_f(unsigned int k) {
    return (k & 0x80000000u) ? __uint_as_float(k & 0x7fffffffu) : __uint_as_float(~k);
}
__device__ __forceinline__ uint32_t smem_u32(const void* p) {
    uint32_t a;
    asm("{ .reg .u64 t; cvta.to.shared.u64 t, %1; cvt.u32.u64 %0, t; }" : "=r"(a) : "l"(p));
    return a;
}
__device__ __forceinline__ uint32_t packh2(float a, float b) {
    __half2 t = __floats2half2_rn(a, b);
    return reinterpret_cast<uint32_t&>(t);
}
// fp16 hi/lo split: hi = rn(x), lo = rn(x - hi). Reconstruction exact to ~2^-23.
__device__ __forceinline__ void split2h(float a, float b, uint32_t& hi, uint32_t& lo) {
    __half ha = __float2half_rn(a), hb = __float2half_rn(b);
    float ra = a - __half2float(ha), rb = b - __half2float(hb);
    __half2 H; H.x = ha; H.y = hb;
    hi = reinterpret_cast<uint32_t&>(H);
    lo = packh2(ra, rb);
}

// ---------------- cp.async helpers ------------------------------------------
__device__ __forceinline__ void cp16(uint32_t saddr, const void* gptr) {
    asm volatile("cp.async.cg.shared.global [%0], [%1], 16;" :: "r"(saddr), "l"(gptr));
}
#define CP_COMMIT() asm volatile("cp.async.commit_group;" ::: "memory")
#define CP_WAIT0()  asm volatile("cp.async.wait_group 0;" ::: "memory")

// ---------------- mma.sync + ldmatrix helpers -------------------------------
__device__ __forceinline__ void ldsm_x4(uint32_t* r, uint32_t addr) {
    asm volatile("ldmatrix.sync.aligned.m8n8.x4.shared.b16 {%0,%1,%2,%3}, [%4];"
        : "=r"(r[0]), "=r"(r[1]), "=r"(r[2]), "=r"(r[3]) : "r"(addr));
}
__device__ __forceinline__ void ldsm_x2(uint32_t* r, uint32_t addr) {
    asm volatile("ldmatrix.sync.aligned.m8n8.x2.shared.b16 {%0,%1}, [%2];"
        : "=r"(r[0]), "=r"(r[1]) : "r"(addr));
}
__device__ __forceinline__ void ldsm_x4t(uint32_t* r, uint32_t addr) {
    asm volatile("ldmatrix.sync.aligned.m8n8.x4.trans.shared.b16 {%0,%1,%2,%3}, [%4];"
        : "=r"(r[0]), "=r"(r[1]), "=r"(r[2]), "=r"(r[3]) : "r"(addr));
}
__device__ __forceinline__ void ldsm_x2t(uint32_t* r, uint32_t addr) {
    asm volatile("ldmatrix.sync.aligned.m8n8.x2.trans.shared.b16 {%0,%1}, [%2];"
        : "=r"(r[0]), "=r"(r[1]) : "r"(addr));
}
__device__ __forceinline__ void mma_f16(float* c, const uint32_t* a, const uint32_t* b) {
    asm volatile("mma.sync.aligned.m16n8k16.row.col.f32.f16.f16.f32 "
        "{%0,%1,%2,%3}, {%4,%5,%6,%7}, {%8,%9}, {%0,%1,%2,%3};"
        : "+f"(c[0]), "+f"(c[1]), "+f"(c[2]), "+f"(c[3])
        : "r"(a[0]), "r"(a[1]), "r"(a[2]), "r"(a[3]), "r"(b[0]), "r"(b[1]));
}

// ---------------------------------------------------------------------------
__global__ void init_kernel() {
    if (threadIdx.x == 0 && blockIdx.x == 0) g_kmax_enc = 0u;
}

// prep_proj: proj -> single fp16 pairs, rows padded to 384 with zeros.
__global__ void prep_proj(const float* __restrict__ proj) {
    int i = blockIdx.x * blockDim.x + threadIdx.x;
    if (i >= 384 * 32) return;
    int r = i >> 5, p = i & 31;
    float2 v = (r < MFEAT) ? *(const float2*)(proj + r * 64 + 2 * p) : make_float2(0.f, 0.f);
    g_pjf[i] = packh2(v.x, v.y);
}

// ---------------------------------------------------------------------------
// ctx_fused: GEMM1 = proj(fp16 hi/lo) @ k(single fp16)^T, 2-term fp16;
// diag from STAGED smem fp16 (consistent with GEMM operand); block max ->
// rescale -> kp fp16 in regs -> GEMM2 kpT @ [v|1] fp16 single product.
// grid (3*KSPL, BH), block 256, 2 CTAs/SM.
// ---------------------------------------------------------------------------
#define CP_H 0
#define CP_L 18432
#define CK_  36864
#define CW_  46080
#define CD_  57344
#define C_MX 57600
#define CX_SZ 57664

__global__ void __launch_bounds__(256, 2) ctx_fused(const float* __restrict__ k_in,
                                                    const float* __restrict__ v_in,
                                                    const float* __restrict__ proj) {
    extern __shared__ char smem[];
    uint32_t sb = smem_u32(smem);
    int tid = threadIdx.x, w = tid >> 5, lane = tid & 31;
    int bh = blockIdx.y, mtile = blockIdx.x % 3, ks = blockIdx.x / 3;

    int arow = lane & 15, koff = (lane >> 4) * 16;
    int br7 = lane & 7, bk8 = ((lane >> 3) & 1) * 16;
    int mh16 = (lane >> 4) & 1;
    int krb  = (lane & 7) + 8 * ((lane >> 3) & 1);
    int qrow = lane >> 2, qcol2 = 2 * (lane & 3);
    int tileid = 8 * mtile + w;
    bool wvalid = tileid <= 16;
    int mr0 = mtile * 128 + 16 * w + qrow;

    // stage proj tile [128 m rows x 64 d] fp16 hi/lo (persistent)
    for (int i = tid; i < 128 * 32; i += 256) {
        int r = i >> 5, p = i & 31;
        int m = mtile * 128 + r;
        float2 v = (m < MFEAT) ? *(const float2*)(proj + m * 64 + 2 * p) : make_float2(0.f, 0.f);
        uint32_t hi, lo; split2h(v.x, v.y, hi, lo);
        *(uint32_t*)(smem + CP_H + r * 144 + 4 * p) = hi;
        *(uint32_t*)(smem + CP_L + r * 144 + 4 * p) = lo;
    }

    float accC[9][4];
    #pragma unroll
    for (int n = 0; n < 9; n++)
        #pragma unroll
        for (int x = 0; x < 4; x++) accC[n][x] = 0.f;
    float Mold = NEGINF;

    #pragma unroll 1
    for (int c = 0; c < KSEG / 64; c++) {
        int n0 = ks * KSEG + c * 64;
        __syncthreads();
        const float* kb = k_in + ((size_t)bh * NSEQ + n0) * DDIM;
        for (int i = tid; i < 64 * 32; i += 256) {
            int r = i >> 5, p = i & 31;
            float2 v = *(const float2*)(kb + r * 64 + 2 * p);
            *(uint32_t*)(smem + CK_ + r * 144 + 4 * p) = packh2(DNORM * v.x, DNORM * v.y);
        }
        const float* vb = v_in + ((size_t)bh * NSEQ + n0) * DDIM;
        for (int i = tid; i < 64 * 36; i += 256) {
            int r = i / 36, p = i % 36;
            int e = 2 * p;
            float2 wv;
            if (e < 64)       wv = *(const float2*)(vb + r * 64 + e);
            else if (e == 64) wv = make_float2(1.f, 0.f);
            else              wv = make_float2(0.f, 0.f);
            *(uint32_t*)(smem + CW_ + r * 176 + 4 * p) = packh2(wv.x, wv.y);
        }
        __syncthreads();

        // diag from STAGED fp16 (smem; matches GEMM operand). 0.5*sum (DN x)^2
        if (tid < 64) {
            float s = 0.f;
            #pragma unroll
            for (int p = 0; p < 32; p++) {
                uint32_t u = *(uint32_t*)(smem + CK_ + tid * 144 + 4 * p);
                __half2 h2 = reinterpret_cast<__half2&>(u);
                float x0 = __half2float(h2.x), x1 = __half2float(h2.y);
                s += x0 * x0 + x1 * x1;
            }
            ((float*)(smem + CD_))[tid] = 0.5f * s;
        }
        __syncthreads();

        // GEMM1': ddT[16 rows x 64 n], 2-term fp16 (A split, B single)
        float c1[8][4];
        #pragma unroll
        for (int n = 0; n < 8; n++)
            #pragma unroll
            for (int x = 0; x < 4; x++) c1[n][x] = 0.f;
        if (wvalid) {
            #pragma unroll
            for (int kt = 0; kt < 4; kt++) {
                uint32_t aph[4], apl[4];
                uint32_t a = sb + CP_H + (uint32_t)(16 * w + arow) * 144 + kt * 32 + koff;
                ldsm_x4(aph, a);
                ldsm_x4(apl, a + (CP_L - CP_H));
                uint32_t bk[8][2];
                #pragma unroll
                for (int np = 0; np < 4; np++) {
                    uint32_t nrow = (uint32_t)(8 * (2 * np + mh16) + br7);
                    ldsm_x4(&bk[2 * np][0], sb + CK_ + nrow * 144 + kt * 32 + bk8);
                }
                #pragma unroll
                for (int n = 0; n < 8; n++) {
                    mma_f16(c1[n], aph, bk[n]);
                    mma_f16(c1[n], apl, bk[n]);
                }
            }
        }

        bool v0 = wvalid && (mr0 < MFEAT), v1 = wvalid && (mr0 + 8 < MFEAT);
        float lm = NEGINF;
        #pragma unroll
        for (int n = 0; n < 8; n++) {
            if (v0) lm = fmaxf(lm, fmaxf(c1[n][0], c1[n][1]));
            if (v1) lm = fmaxf(lm, fmaxf(c1[n][2], c1[n][3]));
        }
        #pragma unroll
        for (int off = 16; off; off >>= 1) lm = fmaxf(lm, __shfl_xor_sync(0xffffffffu, lm, off));
        if (lane == 0) ((float*)(smem + C_MX))[w] = lm;
        __syncthreads();
        float bmax = NEGINF;
        #pragma unroll
        for (int i = 0; i < 8; i++) bmax = fmaxf(bmax, ((float*)(smem + C_MX))[i]);
        float Mnew = fmaxf(Mold, bmax);

        if (wvalid) {
            float factor = __expf(Mold - Mnew);
            float f0 = (mr0 == MFEAT) ? 1.f : factor;
            float f1 = (mr0 + 8 == MFEAT) ? 1.f : factor;
            #pragma unroll
            for (int n = 0; n < 9; n++) {
                accC[n][0] *= f0; accC[n][1] *= f0;
                accC[n][2] *= f1; accC[n][3] *= f1;
            }

            float* dg = (float*)(smem + CD_);
            #pragma unroll
            for (int kt2 = 0; kt2 < 4; kt2++) {
                int u = 2 * kt2, vt = u + 1;
                int ncol = 16 * kt2 + qcol2;
                float dgu0 = dg[ncol],     dgu1 = dg[ncol + 1];
                float dgv0 = dg[ncol + 8], dgv1 = dg[ncol + 9];
                uint32_t qa[4];
                {
                    float a0, a1, a2, a3;
                    if (mr0 < MFEAT) {
                        a0 = RATIO_C * __expf(c1[u][0] - dgu0 - Mnew);
                        a1 = RATIO_C * __expf(c1[u][1] - dgu1 - Mnew);
                        a2 = RATIO_C * __expf(c1[vt][0] - dgv0 - Mnew);
                        a3 = RATIO_C * __expf(c1[vt][1] - dgv1 - Mnew);
                    } else if (mr0 == MFEAT) { a0 = a1 = a2 = a3 = 1.f; }
                    else { a0 = a1 = a2 = a3 = 0.f; }
                    qa[0] = packh2(a0, a1); qa[2] = packh2(a2, a3);
                }
                {
                    int m1 = mr0 + 8;
                    float a0, a1, a2, a3;
                    if (m1 < MFEAT) {
                        a0 = RATIO_C * __expf(c1[u][2] - dgu0 - Mnew);
                        a1 = RATIO_C * __expf(c1[u][3] - dgu1 - Mnew);
                        a2 = RATIO_C * __expf(c1[vt][2] - dgv0 - Mnew);
                        a3 = RATIO_C * __expf(c1[vt][3] - dgv1 - Mnew);
                    } else if (m1 == MFEAT) { a0 = a1 = a2 = a3 = 1.f; }
                    else { a0 = a1 = a2 = a3 = 0.f; }
                    qa[1] = packh2(a0, a1); qa[3] = packh2(a2, a3);
                }
                uint32_t bwh[9][2];
                uint32_t wrow = sb + CW_ + (uint32_t)(kt2 * 16 + krb) * 176;
                #pragma unroll
                for (int np = 0; np < 4; np++)
                    ldsm_x4t(&bwh[2 * np][0], wrow + 16 * (uint32_t)(2 * np + mh16));
                ldsm_x2t(bwh[8], wrow + 128);
                #pragma unroll
                for (int nE = 0; nE < 9; nE++)
                    mma_f16(accC[nE], qa, bwh[nE]);
            }
        }
        Mold = Mnew;
    }

    if (wvalid) {
        float* slab = g_ctxS + ((size_t)(ks * BH + bh)) * 72 * MP;
        #pragma unroll
        for (int nE = 0; nE < 9; nE++) {
            int e = 8 * nE + qcol2;
            slab[(size_t)e * MP + mr0]           = accC[nE][0];
            slab[(size_t)(e + 1) * MP + mr0]     = accC[nE][1];
            slab[(size_t)e * MP + mr0 + 8]       = accC[nE][2];
            slab[(size_t)(e + 1) * MP + mr0 + 8] = accC[nE][3];
        }
    }
    if (tid == 0) {
        g_ctxM[(ks * BH + bh) * 3 + mtile] = Mold;
        atomicMax(&g_kmax_enc, enc_f(Mold));
    }
}

// ---------------------------------------------------------------------------
// convert: VERBATIM R16.
// ---------------------------------------------------------------------------
__global__ void __launch_bounds__(160) convert_kernel() {
    __shared__ float sc[KSPL * 3];
    __shared__ float vs_sh;
    __shared__ float red[5];
    int e = blockIdx.x, bh = blockIdx.y, t = threadIdx.x;
    float G = dec_f(g_kmax_enc);
    if (t < KSPL * 3) sc[t] = __expf(g_ctxM[(t / 3 * BH + bh) * 3 + (t % 3)] - G);
    if (t == 0) {
        float v = 0.f;
        #pragma unroll
        for (int ks = 0; ks < KSPL; ks++)
            v += g_ctxS[(((size_t)(ks * BH + bh)) * 72 + e) * MP + MFEAT];
        vs_sh = v;
    }
    __syncthreads();

    int mt = t >> 6;
    int m0 = 2 * t;
    float sx = 0.f, sy = 0.f;
    if (m0 < 272) {
        #pragma unroll
        for (int ks = 0; ks < KSPL; ks++) {
            float2 vv = *(const float2*)(g_ctxS + (((size_t)(ks * BH + bh)) * 72 + e) * MP + m0);
            float s = sc[ks * 3 + mt];
            sx += s * vv.x; sy += s * vv.y;
        }
    }
    float eps_add = REPS_C * vs_sh;
    float fx = (m0     < MFEAT) ? sx + eps_add : 0.f;
    float fy = (m0 + 1 < MFEAT) ? sy + eps_add : 0.f;
    g_ctf[((size_t)bh * 72 + e) * 160 + t] = packh2(fx, fy);

    float part = fx + fy;
    #pragma unroll
    for (int off = 16; off; off >>= 1) part += __shfl_xor_sync(0xffffffffu, part, off);
    if ((t & 31) == 0) red[t >> 5] = part;
    __syncthreads();
    if (t == 0) g_ctxsum[bh * 72 + e] = red[0] + red[1] + red[2] + red[3] + red[4];
}

// ---------------------------------------------------------------------------
// out_fused: VERBATIM R16 (fp16 2-term GEMM1 + cp.async pipeline).
// ---------------------------------------------------------------------------
#define OQ_H 0
#define OQ_L 18432
#define OPB  36864           // 2 bufs x 9216 (single fp16 proj)
#define OCB  55296           // 2 bufs x 10368
#define O_DG 76032
#define O_SZ 76544

__global__ void __launch_bounds__(256, 2) out_fused(const float* __restrict__ q_in,
                                                    float* __restrict__ out) {
    extern __shared__ char smem[];
    uint32_t sb = smem_u32(smem);
    int tid = threadIdx.x, w = tid >> 5, lane = tid & 31;
    int bh = blockIdx.y, nt = blockIdx.x;
    const float* qb = q_in + ((size_t)bh * NSEQ + nt * 128) * DDIM;

    for (int i = tid; i < 128 * 32; i += 256) {
        int r = i >> 5, p = i & 31;
        float2 v = *(const float2*)(qb + r * 64 + 2 * p);
        uint32_t hi, lo; split2h(DNORM * v.x, DNORM * v.y, hi, lo);
        *(uint32_t*)(smem + OQ_H + r * 144 + 4 * p) = hi;
        *(uint32_t*)(smem + OQ_L + r * 144 + 4 * p) = lo;
    }
    if (tid < 128) {
        float s = 0.f;
        #pragma unroll
        for (int d = 0; d < DDIM; d++) { float x = qb[tid * 64 + d]; s += x * x; }
        ((float*)(smem + O_DG))[tid] = 0.0625f * s;
    }
    // prologue: stage chunk 0
    {
        uint32_t opb = sb + OPB, ocb = sb + OCB;
        for (int i = tid; i < 512; i += 256) {
            int r = i >> 3, cc = i & 7;
            cp16(opb + r * 144 + 16 * cc, g_pjf + (size_t)r * 32 + 4 * cc);
        }
        for (int i = tid; i < 576; i += 256) {
            int r = i >> 3, cc = i & 7;
            cp16(ocb + r * 144 + 16 * cc, g_ctf + ((size_t)bh * 72 + r) * 160 + 4 * cc);
        }
        CP_COMMIT();
    }

    int arow = lane & 15, koff = (lane >> 4) * 16;
    int br7 = lane & 7, bk8 = ((lane >> 3) & 1) * 16;
    int mh16 = (lane >> 4) & 1;
    int qrow = lane >> 2, qcol2 = 2 * (lane & 3);
    int m0 = 16 * w;
    float M0 = NEGINF, M1 = NEGINF;
    float dg0 = 0.f, dg1 = 0.f;

    float accO[9][4];
    #pragma unroll
    for (int n = 0; n < 9; n++)
        #pragma unroll
        for (int x = 0; x < 4; x++) accO[n][x] = 0.f;

    #pragma unroll 1
    for (int ch = 0; ch < 5; ch++) {
        CP_WAIT0();
        __syncthreads();
        if (ch == 0) {
            dg0 = ((float*)(smem + O_DG))[m0 + qrow];
            dg1 = ((float*)(smem + O_DG))[m0 + qrow + 8];
        }
        if (ch + 1 < 5) {
            uint32_t opb = sb + OPB + ((ch + 1) & 1) * 9216;
            uint32_t ocb = sb + OCB + ((ch + 1) & 1) * 10368;
            for (int i = tid; i < 512; i += 256) {
                int r = i >> 3, cc = i & 7;
                cp16(opb + r * 144 + 16 * cc, g_pjf + (size_t)((ch + 1) * 64 + r) * 32 + 4 * cc);
            }
            for (int i = tid; i < 576; i += 256) {
                int r = i >> 3, cc = i & 7;
                cp16(ocb + r * 144 + 16 * cc, g_ctf + ((size_t)bh * 72 + r) * 160 + 32 * (ch + 1) + 4 * cc);
            }
            CP_COMMIT();
        }

        uint32_t opb = sb + OPB + (ch & 1) * 9216;
        uint32_t ocb = sb + OCB + (ch & 1) * 10368;

        if (ch < 4) {
            float a1[8][4];
            #pragma unroll
            for (int n = 0; n < 8; n++)
                #pragma unroll
                for (int x = 0; x < 4; x++) a1[n][x] = 0.f;
            #pragma unroll
            for (int kt = 0; kt < 4; kt++) {
                uint32_t ah[4], al[4];
                uint32_t a = sb + OQ_H + (uint32_t)(m0 + arow) * 144 + kt * 32 + koff;
                ldsm_x4(ah, a);
                ldsm_x4(al, a + (OQ_L - OQ_H));
                uint32_t bp[8][2];
                #pragma unroll
                for (int np = 0; np < 4; np++) {
                    uint32_t nrow = (uint32_t)(8 * (2 * np + mh16) + br7);
                    ldsm_x4(&bp[2 * np][0], opb + nrow * 144 + kt * 32 + bk8);
                }
                #pragma unroll
                for (int n = 0; n < 8; n++) {
                    mma_f16(a1[n], ah, bp[n]);
                    mma_f16(a1[n], al, bp[n]);
                }
            }

            float lm0 = NEGINF, lm1 = NEGINF;
            #pragma unroll
            for (int n = 0; n < 8; n++) {
                lm0 = fmaxf(lm0, fmaxf(a1[n][0], a1[n][1]));
                lm1 = fmaxf(lm1, fmaxf(a1[n][2], a1[n][3]));
            }
            lm0 = fmaxf(lm0, __shfl_xor_sync(0xffffffffu, lm0, 1));
            lm0 = fmaxf(lm0, __shfl_xor_sync(0xffffffffu, lm0, 2));
            lm1 = fmaxf(lm1, __shfl_xor_sync(0xffffffffu, lm1, 1));
            lm1 = fmaxf(lm1, __shfl_xor_sync(0xffffffffu, lm1, 2));
            float Mn0 = fmaxf(M0, lm0), Mn1 = fmaxf(M1, lm1);
            float f0 = __expf(M0 - Mn0), f1 = __expf(M1 - Mn1);
            M0 = Mn0; M1 = Mn1;
            float off0 = dg0 + Mn0, off1 = dg1 + Mn1;
            #pragma unroll
            for (int n = 0; n < 9; n++) {
                accO[n][0] *= f0; accO[n][1] *= f0;
                accO[n][2] *= f1; accO[n][3] *= f1;
            }

            #pragma unroll
            for (int kt2 = 0; kt2 < 4; kt2++) {
                int u = 2 * kt2, vt = u + 1;
                uint32_t qa[4];
                qa[0] = packh2(RATIO_C * __expf(a1[u][0] - off0), RATIO_C * __expf(a1[u][1] - off0));
                qa[2] = packh2(RATIO_C * __expf(a1[vt][0] - off0), RATIO_C * __expf(a1[vt][1] - off0));
                qa[1] = packh2(RATIO_C * __expf(a1[u][2] - off1), RATIO_C * __expf(a1[u][3] - off1));
                qa[3] = packh2(RATIO_C * __expf(a1[vt][2] - off1), RATIO_C * __expf(a1[vt][3] - off1));
                uint32_t cbh[9][2];
                #pragma unroll
                for (int np = 0; np < 4; np++) {
                    uint32_t nrow = (uint32_t)(8 * (2 * np + mh16) + br7);
                    ldsm_x4(&cbh[2 * np][0], ocb + nrow * 144 + kt2 * 32 + bk8);
                }
                ldsm_x2(cbh[8], ocb + (uint32_t)(64 + br7) * 144 + kt2 * 32 + bk8);
                #pragma unroll
                for (int n = 0; n < 9; n++)
                    mma_f16(accO[n], qa, cbh[n]);
            }
        } else {
            // last chunk (m 256..319, valid < 266): 2 n-tiles, kt2=0 only
            float a1[2][4];
            #pragma unroll
            for (int n = 0; n < 2; n++)
                #pragma unroll
                for (int x = 0; x < 4; x++) a1[n][x] = 0.f;
            #pragma unroll
            for (int kt = 0; kt < 4; kt++) {
                uint32_t ah[4], al[4];
                uint32_t a = sb + OQ_H + (uint32_t)(m0 + arow) * 144 + kt * 32 + koff;
                ldsm_x4(ah, a);
                ldsm_x4(al, a + (OQ_L - OQ_H));
                uint32_t bp[2][2];
                uint32_t nrow = (uint32_t)(8 * mh16 + br7);
                ldsm_x4(&bp[0][0], opb + nrow * 144 + kt * 32 + bk8);
                #pragma unroll
                for (int n = 0; n < 2; n++) {
                    mma_f16(a1[n], ah, bp[n]);
                    mma_f16(a1[n], al, bp[n]);
                }
            }

            float lm0 = NEGINF, lm1 = NEGINF;
            #pragma unroll
            for (int n = 0; n < 2; n++) {
                int gm = 256 + 8 * n + qcol2;
                if (gm < MFEAT)     { lm0 = fmaxf(lm0, a1[n][0]); lm1 = fmaxf(lm1, a1[n][2]); }
                if (gm + 1 < MFEAT) { lm0 = fmaxf(lm0, a1[n][1]); lm1 = fmaxf(lm1, a1[n][3]); }
            }
            lm0 = fmaxf(lm0, __shfl_xor_sync(0xffffffffu, lm0, 1));
            lm0 = fmaxf(lm0, __shfl_xor_sync(0xffffffffu, lm0, 2));
            lm1 = fmaxf(lm1, __shfl_xor_sync(0xffffffffu, lm1, 1));
            lm1 = fmaxf(lm1, __shfl_xor_sync(0xffffffffu, lm1, 2));
            float Mn0 = fmaxf(M0, lm0), Mn1 = fmaxf(M1, lm1);
            float f0 = __expf(M0 - Mn0), f1 = __expf(M1 - Mn1);
            M0 = Mn0; M1 = Mn1;
            float off0 = dg0 + Mn0, off1 = dg1 + Mn1;
            #pragma unroll
            for (int n = 0; n < 9; n++) {
                accO[n][0] *= f0; accO[n][1] *= f0;
                accO[n][2] *= f1; accO[n][3] *= f1;
            }

            int gmu = 256 + qcol2, gmv = 264 + qcol2;
            uint32_t qa[4];
            {
                float a0 = (gmu     < MFEAT) ? RATIO_C * __expf(a1[0][0] - off0) : 0.f;
                float a1v = (gmu + 1 < MFEAT) ? RATIO_C * __expf(a1[0][1] - off0) : 0.f;
                float a2 = (gmv     < MFEAT) ? RATIO_C * __expf(a1[1][0] - off0) : 0.f;
                float a3 = (gmv + 1 < MFEAT) ? RATIO_C * __expf(a1[1][1] - off0) : 0.f;
                qa[0] = packh2(a0, a1v); qa[2] = packh2(a2, a3);
            }
            {
                float a0 = (gmu     < MFEAT) ? RATIO_C * __expf(a1[0][2] - off1) : 0.f;
                float a1v = (gmu + 1 < MFEAT) ? RATIO_C * __expf(a1[0][3] - off1) : 0.f;
                float a2 = (gmv     < MFEAT) ? RATIO_C * __expf(a1[1][2] - off1) : 0.f;
                float a3 = (gmv + 1 < MFEAT) ? RATIO_C * __expf(a1[1][3] - off1) : 0.f;
                qa[1] = packh2(a0, a1v); qa[3] = packh2(a2, a3);
            }
            uint32_t cbh[9][2];
            #pragma unroll
            for (int np = 0; np < 4; np++) {
                uint32_t nrow = (uint32_t)(8 * (2 * np + mh16) + br7);
                ldsm_x4(&cbh[2 * np][0], ocb + nrow * 144 + bk8);
            }
            ldsm_x2(cbh[8], ocb + (uint32_t)(64 + br7) * 144 + bk8);
            #pragma unroll
            for (int n = 0; n < 9; n++)
                mma_f16(accO[n], qa, cbh[n]);
        }
    }

    #pragma unroll
    for (int n = 0; n < 9; n++) {
        int col = 8 * n + qcol2;
        float cs0 = g_ctxsum[bh * 72 + col];
        float cs1 = g_ctxsum[bh * 72 + col + 1];
        accO[n][0] += REPS_C * cs0; accO[n][1] += REPS_C * cs1;
        accO[n][2] += REPS_C * cs0; accO[n][3] += REPS_C * cs1;
    }
    float d0 = __shfl_sync(0xffffffffu, accO[8][0], lane & ~3);
    float d1 = __shfl_sync(0xffffffffu, accO[8][2], lane & ~3);
    float i0 = 1.0f / d0, i1 = 1.0f / d1;
    int r0g = nt * 128 + m0 + qrow;
    float* ob = out + (size_t)bh * NSEQ * DDIM;
    #pragma unroll
    for (int n = 0; n < 8; n++) {
        int col = 8 * n + qcol2;
        *(float2*)(ob + (size_t)r0g * DDIM + col) = make_float2(i0 * accO[n][0], i0 * accO[n][1]);
        *(float2*)(ob + (size_t)(r0g + 8) * DDIM + col) = make_float2(i1 * accO[n][2], i1 * accO[n][3]);
    }
}

// ---------------------------------------------------------------------------
extern "C" void kernel_launch(void* const* d_in, const int* in_sizes, int n_in,
                              void* d_out, int out_size) {
    const float* q    = (const float*)d_in[0];
    const float* k    = (const float*)d_in[1];
    const float* v    = (const float*)d_in[2];
    const float* proj = (const float*)d_in[3];
    float* out = (float*)d_out;

    cudaFuncSetAttribute(ctx_fused, cudaFuncAttributeMaxDynamicSharedMemorySize, CX_SZ);
    cudaFuncSetAttribute(out_fused, cudaFuncAttributeMaxDynamicSharedMemorySize, O_SZ);

    init_kernel<<<1, 32>>>();
    prep_proj<<<48, 256>>>(proj);
    ctx_fused<<<dim3(3 * KSPL, BH), 256, CX_SZ>>>(k, v, proj);
    convert_kernel<<<dim3(72, BH), 160>>>();
    out_fused<<<dim3(NT, BH), 256, O_SZ>>>(q, out);
}